// round 17
// baseline (speedup 1.0000x reference)
#include <cuda_runtime.h>
#include <math.h>

// Problem dims
#define B_DIM 32
#define F_DIM 1024
#define NG    25
#define NFRM  (B_DIM * F_DIM)
#define FPC   4                       // frames per CTA (2 packed groups of 2)

typedef unsigned long long u64;

// gli scratch, CHANNEL-MAJOR: g_gli[c * NFRM + bf]  (coalesced vel reads)
__device__ float g_gli[NG * NFRM];

// Segment tables (16 segments across 5 paths)
// paths: [2,5,8,11], [1,4,7,10], [3,6,9,12,15], [14,17,19,21], [13,16,18,20]
__constant__ unsigned char c_ss[16]   = {2,5,8, 1,4,7, 3,6,9,12, 14,17,19, 13,16,18};
__constant__ unsigned char c_se[16]   = {5,8,11, 4,7,10, 6,9,12,15, 17,19,21, 16,18,20};
__constant__ unsigned char c_base[5]  = {0,3,6,10,13};
__constant__ unsigned char c_cnt[5]   = {3,3,4,3,3};

// ---- packed f32x2 helpers (sm_100+; ptxas never auto-fuses these) ----
__device__ __forceinline__ u64 fma2(u64 a, u64 b, u64 c) {
    u64 d; asm("fma.rn.f32x2 %0,%1,%2,%3;" : "=l"(d) : "l"(a), "l"(b), "l"(c)); return d;
}
__device__ __forceinline__ u64 mul2(u64 a, u64 b) {
    u64 d; asm("mul.rn.f32x2 %0,%1,%2;" : "=l"(d) : "l"(a), "l"(b)); return d;
}
__device__ __forceinline__ u64 add2(u64 a, u64 b) {
    u64 d; asm("add.rn.f32x2 %0,%1,%2;" : "=l"(d) : "l"(a), "l"(b)); return d;
}
__device__ __forceinline__ u64 pk(float a, float b) {
    u64 d; asm("mov.b64 %0,{%1,%2};" : "=l"(d) : "f"(a), "f"(b)); return d;
}
__device__ __forceinline__ void unpk(u64 v, float& a, float& b) {
    asm("mov.b64 {%0,%1},%2;" : "=f"(a), "=f"(b) : "l"(v));
}
#define NEG1_2 0xBF800000BF800000ULL   // {-1.0f, -1.0f}

// Branch-free asin, A&S 4.4.46 (abs err <= 2e-8), MUFU-only sqrt:
__device__ __forceinline__ float fast_asin(float v) {
    float x = fabsf(v);
    float p = fmaf(x, -0.0012624911f,  0.0066700901f);
    p = fmaf(p, x, -0.0170881256f);
    p = fmaf(p, x,  0.0308918810f);
    p = fmaf(p, x, -0.0501743046f);
    p = fmaf(p, x,  0.0889789874f);
    p = fmaf(p, x, -0.2145988016f);
    p = fmaf(p, x,  1.5707963050f);
    float y = 1.0f - x;                 // >= 1e-7 after clip
    float s = y * rsqrtf(y);            // sqrt via MUFU.RSQ, no IEEE slow path
    float r = fmaf(-s, p, 1.57079632679f);
    return copysignf(r, v);
}

// asin( clip( d / sqrt(qa*qb) ) ), zero-norm -> 0 (matches reference where())
__device__ __forceinline__ float edge_term(float d, float qa, float qb) {
    float p = qa * qb;
    float r = rsqrtf(p);
    float v = (p > 0.f) ? d * r : 0.f;
    v = fminf(fmaxf(v, -1.f + 1e-7f), 1.f - 1e-7f);
    return fast_asin(v);
}

__global__ __launch_bounds__(256)
void gli_kernel(const float* __restrict__ m1, const float* __restrict__ m2)
{
    // Tables pre-interleaved as {frameA, frameB} f32x2 per component.
    __shared__ u64  J1p[2][22][3];
    __shared__ u64  J2p[2][22][3];
    __shared__ u64  R12p[2][16][3];
    __shared__ u64  R34p[2][16][3];
    __shared__ float gall[FPC][256];
    __shared__ unsigned char ss[16];

    const int t   = threadIdx.x;
    const int bf0 = blockIdx.x * FPC;

    // Load phase: 128 lanes per group stage that group's interleaved tables.
    {
        const int g  = t >> 7;              // group 0/1
        const int u  = t & 127;
        const float* bA1 = m1 + (bf0 + 2*g)     * 66;
        const float* bB1 = m1 + (bf0 + 2*g + 1) * 66;
        const float* bA2 = m2 + (bf0 + 2*g)     * 66;
        const float* bB2 = m2 + (bf0 + 2*g + 1) * 66;
        if (u < 22) {
            #pragma unroll
            for (int c = 0; c < 3; c++)
                J1p[g][u][c] = pk(bA1[3*u + c], bB1[3*u + c]);
        } else if (u < 44) {
            int a = u - 22;
            #pragma unroll
            for (int c = 0; c < 3; c++)
                J2p[g][a][c] = pk(bA2[3*a + c], bB2[3*a + c]);
        } else if (u < 60) {
            int i = u - 44;
            int s = 3 * (int)c_ss[i], e = 3 * (int)c_se[i];
            #pragma unroll
            for (int c = 0; c < 3; c++) {
                R12p[g][i][c] = pk(bA1[e+c] - bA1[s+c], bB1[e+c] - bB1[s+c]);
                R34p[g][i][c] = pk(bA2[e+c] - bA2[s+c], bB2[e+c] - bB2[s+c]);
            }
        }
        if (t < 16) ss[t] = c_ss[t];
    }
    __syncthreads();

    // ---- per-pair Gauss integral; geometry packed f32x2 over frame pairs ----
    // P = r13 x r34, Q = r12 x r13, R = r12 x r34
    // f0 = P, f1 = Q+R, f2 = R-P, f3 = -Q, sign flip when (R . r13) >= 0
    const int i  = t >> 4;              // motion1 segment
    const int j  = t & 15;              // motion2 segment
    const int si = (int)ss[i];
    const int sj = (int)ss[j];

    #pragma unroll 1
    for (int g = 0; g < 2; g++) {
        const u64 p1x = J1p[g][si][0], p1y = J1p[g][si][1], p1z = J1p[g][si][2];
        const u64 p2x = J2p[g][sj][0], p2y = J2p[g][sj][1], p2z = J2p[g][sj][2];
        const u64 Ax  = R12p[g][i][0], Ay  = R12p[g][i][1], Az  = R12p[g][i][2];
        const u64 Bx  = R34p[g][j][0], By  = R34p[g][j][1], Bz  = R34p[g][j][2];

        // r13 = p2 - p1
        const u64 rx = fma2(p1x, NEG1_2, p2x);
        const u64 ry = fma2(p1y, NEG1_2, p2y);
        const u64 rz = fma2(p1z, NEG1_2, p2z);

        const u64 Anx = mul2(Ax, NEG1_2), Any = mul2(Ay, NEG1_2), Anz = mul2(Az, NEG1_2);
        const u64 Bnx = mul2(Bx, NEG1_2), Bny = mul2(By, NEG1_2), Bnz = mul2(Bz, NEG1_2);

        // P = r13 x B
        const u64 Px = fma2(ry, Bz, mul2(rz, Bny));
        const u64 Py = fma2(rz, Bx, mul2(rx, Bnz));
        const u64 Pz = fma2(rx, By, mul2(ry, Bnx));
        // Q = A x r13
        const u64 Qx = fma2(Ay, rz, mul2(Anz, ry));
        const u64 Qy = fma2(Az, rx, mul2(Anx, rz));
        const u64 Qz = fma2(Ax, ry, mul2(Any, rx));
        // R = A x B
        const u64 Rx = fma2(Ay, Bz, mul2(Anz, By));
        const u64 Ry = fma2(Az, Bx, mul2(Anx, Bz));
        const u64 Rz = fma2(Ax, By, mul2(Any, Bx));

        const u64 f1x = add2(Qx, Rx), f1y = add2(Qy, Ry), f1z = add2(Qz, Rz);
        const u64 f2x = fma2(Px, NEG1_2, Rx), f2y = fma2(Py, NEG1_2, Ry), f2z = fma2(Pz, NEG1_2, Rz);

        const u64 q0 = fma2(Pz,  Pz,  fma2(Py,  Py,  mul2(Px,  Px)));
        const u64 q1 = fma2(f1z, f1z, fma2(f1y, f1y, mul2(f1x, f1x)));
        const u64 q2 = fma2(f2z, f2z, fma2(f2y, f2y, mul2(f2x, f2x)));
        const u64 q3 = fma2(Qz,  Qz,  fma2(Qy,  Qy,  mul2(Qx,  Qx)));

        const u64 d01 = fma2(Pz,  f1z, fma2(Py,  f1y, mul2(Px,  f1x)));   //  f0.f1
        const u64 d12 = fma2(f1z, f2z, fma2(f1y, f2y, mul2(f1x, f2x)));   //  f1.f2
        const u64 d23 = fma2(f2z, Qz,  fma2(f2y, Qy,  mul2(f2x, Qx)));    // -(f2.f3)
        const u64 d30 = fma2(Pz,  Qz,  fma2(Py,  Qy,  mul2(Px,  Qx)));    // -(f3.f0)

        const u64 rr2 = fma2(Rz, rz, fma2(Ry, ry, mul2(Rx, rx)));         //  R.r13

        float d01a, d01b, d12a, d12b, d23a, d23b, d30a, d30b;
        float q0a, q0b, q1a, q1b, q2a, q2b, q3a, q3b, rra, rrb;
        unpk(d01, d01a, d01b); unpk(d12, d12a, d12b);
        unpk(d23, d23a, d23b); unpk(d30, d30a, d30b);
        unpk(q0, q0a, q0b); unpk(q1, q1a, q1b);
        unpk(q2, q2a, q2b); unpk(q3, q3a, q3b);
        unpk(rr2, rra, rrb);

        float ga = edge_term(d01a, q0a, q1a)
                 + edge_term(d12a, q1a, q2a)
                 - edge_term(d23a, q2a, q3a)
                 - edge_term(d30a, q3a, q0a);
        float gb = edge_term(d01b, q0b, q1b)
                 + edge_term(d12b, q1b, q2b)
                 - edge_term(d23b, q2b, q3b)
                 - edge_term(d30b, q3b, q0b);

        ga = (rra >= 0.f) ? -ga : ga;       // == original sgn=-(R.r13); flip if sgn<=0
        gb = (rrb >= 0.f) ? -gb : gb;
        gall[2*g    ][t] = ga * 0.07957747154594767f;   // 1/(4*pi)
        gall[2*g + 1][t] = gb * 0.07957747154594767f;
    }
    __syncthreads();

    // Deterministic fixed-order reduction; 4 frames reduced concurrently
    // (frame ff handled by lanes [64*ff, 64*ff+25)).
    {
        const int ff = t >> 6;
        const int c  = t & 63;
        if (c < NG) {
            const int pa = c / 5;
            const int pb = c - 5 * pa;
            const int i0 = c_base[pa], na = c_cnt[pa];
            const int j0 = c_base[pb], nb = c_cnt[pb];
            float s = 0.f;
            for (int u = 0; u < na; u++)
                for (int v = 0; v < nb; v++)
                    s += gall[ff][(i0 + u) * 16 + (j0 + v)];
            g_gli[c * NFRM + (bf0 + ff)] = s;    // channel-major
        }
    }
}

// Velocity: 2 threads per output, channel-major coalesced loads, butterfly max.
__global__ __launch_bounds__(256)
void vel_kernel(float* __restrict__ out)
{
    const int n = B_DIM * (F_DIM - 1);
    int gid  = blockIdx.x * blockDim.x + threadIdx.x;
    int idx  = gid >> 1;
    int h    = gid & 1;
    if (idx >= n) return;
    int b  = idx / (F_DIM - 1);
    int f  = idx - b * (F_DIM - 1);
    int bf = b * F_DIM + f;
    float m = 0.f;
#pragma unroll
    for (int c = h; c < NG; c += 2) {
        float a0 = g_gli[c * NFRM + bf];
        float a1 = g_gli[c * NFRM + bf + 1];
        m = fmaxf(m, fabsf(a1 - a0));
    }
    m = fmaxf(m, __shfl_xor_sync(0xffffffffu, m, 1));
    if (h == 0) out[idx] = m;
}

extern "C" void kernel_launch(void* const* d_in, const int* in_sizes, int n_in,
                              void* d_out, int out_size)
{
    const float* m1 = (const float*)d_in[0];   // motion1 (32,1024,22,3) f32
    const float* m2 = (const float*)d_in[1];   // motion2 (32,1024,22,3) f32
    float* out = (float*)d_out;                // (32,1023) f32

    gli_kernel<<<NFRM / FPC, 256>>>(m1, m2);

    const int nthreads = B_DIM * (F_DIM - 1) * 2;
    vel_kernel<<<(nthreads + 255) / 256, 256>>>(out);
}